// round 2
// baseline (speedup 1.0000x reference)
#include <cuda_runtime.h>

#define NB 1024
#define NS 50
#define NH 64
#define NITEM 40000
#define TPB 256

__global__ __launch_bounds__(TPB, 2)
void rrd_kernel(const float* __restrict__ all_memory,
                const float* __restrict__ last_memory,
                const int*   __restrict__ seq_item,
                const float* __restrict__ Wr,
                const float* __restrict__ Ur,
                const float* __restrict__ Vr_w,
                float* __restrict__ out)
{
    __shared__ float xs[NS * NH];      // all_memory row   (12.8 KB)
    __shared__ float mat[NH * 65];     // padded Wr, then Ur (16.6 KB)
    __shared__ float lastm[NH];
    __shared__ float scores[64];
    __shared__ float probs[NS];

    const int tid = threadIdx.x;
    const int b   = blockIdx.x;
    const int k   = tid & 63;
    const int g   = tid >> 6;          // 0..3: s-group

    // ---- FIRST: fire the 40000-float zero stores (no deps; drains under compute) ----
    float* row = out + (size_t)b * NITEM;
    float4* row4 = reinterpret_cast<float4*>(row);
    const float4 z = make_float4(0.f, 0.f, 0.f, 0.f);
    #pragma unroll 5
    for (int i = tid; i < NITEM / 4; i += TPB) row4[i] = z;

    // ---- stage inputs into smem (coalesced) ----
    const float* am = all_memory + (size_t)b * (NS * NH);
    for (int i = tid; i < NS * NH; i += TPB) xs[i] = am[i];
    if (tid < NH) lastm[tid] = last_memory[b * NH + tid];
    if (tid < 64) scores[tid] = 0.f;
    for (int i = tid; i < NH * NH; i += TPB) {
        int r = i >> 6, c = i & 63;
        mat[r * 65 + c] = Wr[i];       // pad-65: bank (k+h)%32 conflict-free
    }
    __syncthreads();

    // ---- l_k = sum_h last[h] * Wr[k,h] ----
    float lk = 0.f;
    #pragma unroll
    for (int h = 0; h < NH; h++) lk += lastm[h] * mat[k * 65 + h];
    __syncthreads();

    // ---- reload mat with Ur ----
    for (int i = tid; i < NH * NH; i += TPB) {
        int r = i >> 6, c = i & 63;
        mat[r * 65 + c] = Ur[i];
    }
    __syncthreads();

    // ---- Ur row k into registers ----
    float ur[NH];
    #pragma unroll
    for (int h = 0; h < NH; h++) ur[h] = mat[k * 65 + h];
    const float vk = Vr_w[k];

    // ---- scores: a[s,k] = x[s]·ur ; val = Vr_w[k]*tanh(a+lk) ; reduce over k ----
    for (int s = g; s < NS; s += 4) {
        const float4* xr = reinterpret_cast<const float4*>(xs + s * NH);
        float acc = lk;
        #pragma unroll
        for (int i = 0; i < NH / 4; i++) {
            float4 v = xr[i];                      // broadcast LDS.128
            acc += v.x * ur[4*i]   + v.y * ur[4*i+1]
                 + v.z * ur[4*i+2] + v.w * ur[4*i+3];
        }
        // fast tanh: 1 - 2/(e^{2x}+1); saturates correctly at +/-inf
        float e2x = __expf(2.0f * acc);
        float val = vk * (1.0f - __fdividef(2.0f, e2x + 1.0f));
        #pragma unroll
        for (int o = 16; o; o >>= 1)
            val += __shfl_xor_sync(0xffffffffu, val, o);
        if ((tid & 31) == 0) atomicAdd(&scores[s], val);   // 2 partials/s
    }
    __syncthreads();

    // ---- softmax over S=50 (warp 0); Vr_b cancels under shift-invariance ----
    if (tid < 32) {
        float v0 = (tid      < NS) ? scores[tid]      : -1e30f;
        float v1 = (tid + 32 < NS) ? scores[tid + 32] : -1e30f;
        float m = fmaxf(v0, v1);
        #pragma unroll
        for (int o = 16; o; o >>= 1)
            m = fmaxf(m, __shfl_xor_sync(0xffffffffu, m, o));
        float e0 = (tid      < NS) ? __expf(v0 - m) : 0.f;
        float e1 = (tid + 32 < NS) ? __expf(v1 - m) : 0.f;
        float ssum = e0 + e1;
        #pragma unroll
        for (int o = 16; o; o >>= 1)
            ssum += __shfl_xor_sync(0xffffffffu, ssum, o);
        float inv = 1.f / ssum;
        if (tid      < NS) probs[tid]      = e0 * inv;
        if (tid + 32 < NS) probs[tid + 32] = e1 * inv;
    }

    // ---- orders STG zeros + probs before the scatter atomics (CTA scope) ----
    __syncthreads();

    // ---- scatter-add the 50 probs (atomics handle duplicate items) ----
    if (tid < NS) {
        int item = seq_item[b * NS + tid];
        atomicAdd(row + item, probs[tid]);
    }
}

extern "C" void kernel_launch(void* const* d_in, const int* in_sizes, int n_in,
                              void* d_out, int out_size)
{
    const float* all_memory  = (const float*)d_in[0];
    const float* last_memory = (const float*)d_in[1];
    const int*   seq_item    = (const int*)  d_in[2];
    const float* Wr          = (const float*)d_in[3];
    const float* Ur          = (const float*)d_in[4];
    const float* Vr_w        = (const float*)d_in[5];
    // d_in[6] = Vr_b (scalar) — softmax shift-invariant, unused.
    float* out = (float*)d_out;

    rrd_kernel<<<NB, TPB>>>(all_memory, last_memory, seq_item, Wr, Ur, Vr_w, out);
}

// round 3
// speedup vs baseline: 1.0316x; 1.0316x over previous
#include <cuda_runtime.h>

#define NB 1024
#define NS 50
#define NH 64
#define NITEM 40000
#define TPB 256

// ================= Kernel 1: pure zeroing of out (164 MB) =================
__global__ __launch_bounds__(256)
void zero_kernel(float4* __restrict__ out4, int n4)
{
    int idx    = blockIdx.x * blockDim.x + threadIdx.x;
    int stride = gridDim.x * blockDim.x;
    const float4 z = make_float4(0.f, 0.f, 0.f, 0.f);
    for (int i = idx; i < n4; i += stride)
        out4[i] = z;
}

// ============ Kernel 2: attention scores + softmax + scatter-add ============
__global__ __launch_bounds__(TPB, 2)
void rrd_compute(const float* __restrict__ all_memory,
                 const float* __restrict__ last_memory,
                 const int*   __restrict__ seq_item,
                 const float* __restrict__ Wr,
                 const float* __restrict__ Ur,
                 const float* __restrict__ Vr_w,
                 float* __restrict__ out)
{
    __shared__ float xs[NS * NH];      // all_memory row      (12.8 KB)
    __shared__ float matW[NH * 65];    // padded Wr           (16.6 KB)
    __shared__ float matU[NH * 65];    // padded Ur           (16.6 KB)
    __shared__ float lastm[NH];
    __shared__ float scores[64];
    __shared__ float probs[NS];

    const int tid = threadIdx.x;
    const int b   = blockIdx.x;
    const int k   = tid & 63;
    const int g   = tid >> 6;          // 0..3: s-group

    // ---- stage inputs into smem (coalesced) ----
    const float* am = all_memory + (size_t)b * (NS * NH);
    for (int i = tid; i < NS * NH; i += TPB) xs[i] = am[i];
    if (tid < NH) lastm[tid] = last_memory[b * NH + tid];
    if (tid < 64) scores[tid] = 0.f;
    for (int i = tid; i < NH * NH; i += TPB) {
        int r = i >> 6, c = i & 63;
        matW[r * 65 + c] = Wr[i];      // pad-65: (k+h)%32 conflict-free
        matU[r * 65 + c] = Ur[i];
    }
    __syncthreads();

    // ---- l_k = sum_h last[h] * Wr[k,h] ----
    float lk = 0.f;
    #pragma unroll
    for (int h = 0; h < NH; h++) lk += lastm[h] * matW[k * 65 + h];

    // ---- Ur row k into registers ----
    float ur[NH];
    #pragma unroll
    for (int h = 0; h < NH; h++) ur[h] = matU[k * 65 + h];
    const float vk = Vr_w[k];

    // ---- scores: a[s,k] = x[s]·ur ; val = Vr_w[k]*tanh(a+lk) ; reduce over k ----
    for (int s = g; s < NS; s += 4) {
        const float4* xr = reinterpret_cast<const float4*>(xs + s * NH);
        float acc = lk;
        #pragma unroll
        for (int i = 0; i < NH / 4; i++) {
            float4 v = xr[i];                      // broadcast LDS.128
            acc += v.x * ur[4*i]   + v.y * ur[4*i+1]
                 + v.z * ur[4*i+2] + v.w * ur[4*i+3];
        }
        // fast tanh: 1 - 2/(e^{2x}+1); saturates correctly at +/-inf
        float e2x = __expf(2.0f * acc);
        float val = vk * (1.0f - __fdividef(2.0f, e2x + 1.0f));
        #pragma unroll
        for (int o = 16; o; o >>= 1)
            val += __shfl_xor_sync(0xffffffffu, val, o);
        if ((tid & 31) == 0) atomicAdd(&scores[s], val);   // 2 partials/s
    }
    __syncthreads();

    // ---- softmax over S=50 (warp 0); Vr_b cancels under shift-invariance ----
    if (tid < 32) {
        float v0 = (tid      < NS) ? scores[tid]      : -1e30f;
        float v1 = (tid + 32 < NS) ? scores[tid + 32] : -1e30f;
        float m = fmaxf(v0, v1);
        #pragma unroll
        for (int o = 16; o; o >>= 1)
            m = fmaxf(m, __shfl_xor_sync(0xffffffffu, m, o));
        float e0 = (tid      < NS) ? __expf(v0 - m) : 0.f;
        float e1 = (tid + 32 < NS) ? __expf(v1 - m) : 0.f;
        float ssum = e0 + e1;
        #pragma unroll
        for (int o = 16; o; o >>= 1)
            ssum += __shfl_xor_sync(0xffffffffu, ssum, o);
        float inv = 1.f / ssum;
        if (tid      < NS) probs[tid]      = e0 * inv;
        if (tid + 32 < NS) probs[tid + 32] = e1 * inv;
    }
    __syncthreads();   // publish probs

    // ---- scatter-add the 50 probs (zeros already written by zero_kernel) ----
    if (tid < NS) {
        int item = seq_item[b * NS + tid];
        atomicAdd(out + (size_t)b * NITEM + item, probs[tid]);
    }
}

extern "C" void kernel_launch(void* const* d_in, const int* in_sizes, int n_in,
                              void* d_out, int out_size)
{
    const float* all_memory  = (const float*)d_in[0];
    const float* last_memory = (const float*)d_in[1];
    const int*   seq_item    = (const int*)  d_in[2];
    const float* Wr          = (const float*)d_in[3];
    const float* Ur          = (const float*)d_in[4];
    const float* Vr_w        = (const float*)d_in[5];
    // d_in[6] = Vr_b (scalar) — softmax shift-invariant, unused.
    float* out = (float*)d_out;

    // 1) zero the full output (164 MB) with a saturating pure-store kernel
    int n4 = (NB * NITEM) / 4;                     // 10,240,000 float4s
    zero_kernel<<<5000, 256>>>((float4*)out, n4);

    // 2) compute + scatter (stream-ordered after the zeros)
    rrd_compute<<<NB, TPB>>>(all_memory, last_memory, seq_item, Wr, Ur, Vr_w, out);
}

// round 4
// speedup vs baseline: 1.6453x; 1.5949x over previous
#include <cuda_runtime.h>

#define NB 1024
#define NS 50
#define NH 64
#define NITEM 40000
#define TPB 256
#define STRIDE 6          // 1 compute CTA per 5 zero CTAs
#define ZCHUNK 2000       // float4s per zero CTA: 5120 * 2000 = 10,240,000 exactly

__device__ float g_probs[NB * NS];   // probs scratch between kernels

__global__ __launch_bounds__(TPB, 2)
void fused_kernel(const float* __restrict__ all_memory,
                  const float* __restrict__ last_memory,
                  const float* __restrict__ Wr,
                  const float* __restrict__ Ur,
                  const float* __restrict__ Vr_w,
                  float* __restrict__ out)
{
    const int bid = blockIdx.x;
    const int q   = bid / STRIDE;
    const int tid = threadIdx.x;

    // ================= zero CTAs (5/6 of grid): pure store stream =========
    if (bid - q * STRIDE != 0) {
        const int z = bid - q - 1;               // 0..5119
        float4* p = reinterpret_cast<float4*>(out) + (size_t)z * ZCHUNK;
        const float4 zf = make_float4(0.f, 0.f, 0.f, 0.f);
        #pragma unroll
        for (int i = tid; i < ZCHUNK; i += TPB) p[i] = zf;
        return;
    }

    // ================= compute CTA: one batch row b = q ====================
    const int b = q;

    __shared__ float xs[NS * NH];        // 12.8 KB
    __shared__ float matW[NH * 65];      // 16.6 KB, pad-65 conflict-free
    __shared__ float matU[NH * 65];      // 16.6 KB
    __shared__ float vals[64 * 68];      // 17.4 KB transpose buffer
    __shared__ float lastm[NH];
    __shared__ float scores[64];

    const int k = tid & 63;
    const int g = tid >> 6;              // 0..3 (warp-uniform)

    // ---- stage (float4 loads, scalar padded stores) ----
    const float4* am4 = reinterpret_cast<const float4*>(all_memory + (size_t)b * (NS * NH));
    for (int i = tid; i < NS * NH / 4; i += TPB)
        reinterpret_cast<float4*>(xs)[i] = am4[i];
    if (tid < NH) lastm[tid] = last_memory[b * NH + tid];
    {
        const float4* w4 = reinterpret_cast<const float4*>(Wr);
        const float4* u4 = reinterpret_cast<const float4*>(Ur);
        for (int i = tid; i < NH * NH / 4; i += TPB) {
            int r = i >> 4, c = (i & 15) * 4;
            float4 w = w4[i], u = u4[i];
            float* dw = &matW[r * 65 + c];
            dw[0] = w.x; dw[1] = w.y; dw[2] = w.z; dw[3] = w.w;
            float* du = &matU[r * 65 + c];
            du[0] = u.x; du[1] = u.y; du[2] = u.z; du[3] = u.w;
        }
    }
    __syncthreads();

    // ---- lk = sum_h last[h]*Wr[k,h]  (4 independent accumulators) ----
    float l0 = 0.f, l1 = 0.f, l2 = 0.f, l3 = 0.f;
    #pragma unroll
    for (int h = 0; h < NH; h += 4) {
        l0 += lastm[h]     * matW[k * 65 + h];
        l1 += lastm[h + 1] * matW[k * 65 + h + 1];
        l2 += lastm[h + 2] * matW[k * 65 + h + 2];
        l3 += lastm[h + 3] * matW[k * 65 + h + 3];
    }
    const float lk = (l0 + l1) + (l2 + l3);

    // ---- Ur row k into registers (pad-65: conflict-free) ----
    float ur[NH];
    #pragma unroll
    for (int h = 0; h < NH; h++) ur[h] = matU[k * 65 + h];
    const float vk = Vr_w[k];

    // ---- vals[s][k] = vk * tanh(x[s]·ur + lk), 13 unrolled iters ----
    #pragma unroll
    for (int j = 0; j < 13; j++) {
        const int s = 4 * j + g;                 // warp-uniform
        if (s < NS) {
            const float4* xr = reinterpret_cast<const float4*>(xs + s * NH);
            float a0 = lk, a1 = 0.f, a2 = 0.f, a3 = 0.f;
            #pragma unroll
            for (int i = 0; i < 16; i += 4) {
                float4 v0 = xr[i], v1 = xr[i + 1], v2 = xr[i + 2], v3 = xr[i + 3];
                a0 += v0.x*ur[4*i+ 0] + v0.y*ur[4*i+ 1] + v0.z*ur[4*i+ 2] + v0.w*ur[4*i+ 3];
                a1 += v1.x*ur[4*i+ 4] + v1.y*ur[4*i+ 5] + v1.z*ur[4*i+ 6] + v1.w*ur[4*i+ 7];
                a2 += v2.x*ur[4*i+ 8] + v2.y*ur[4*i+ 9] + v2.z*ur[4*i+10] + v2.w*ur[4*i+11];
                a3 += v3.x*ur[4*i+12] + v3.y*ur[4*i+13] + v3.z*ur[4*i+14] + v3.w*ur[4*i+15];
            }
            float acc = (a0 + a1) + (a2 + a3);
            // fast tanh: 1 - 2/(e^{2x}+1); saturates correctly
            float e2x = __expf(2.0f * acc);
            vals[s * 68 + k] = vk * (1.0f - __fdividef(2.0f, e2x + 1.0f));
        }
    }
    __syncthreads();

    // ---- flat reduction over k: thread (s2,p) sums 16, quad-combine ----
    {
        const int s2 = tid >> 2, p = tid & 3;    // s2: 0..63, p: 0..3
        const float4* vr = reinterpret_cast<const float4*>(vals + s2 * 68 + p * 16);
        float4 r0 = vr[0], r1 = vr[1], r2 = vr[2], r3 = vr[3];
        float sum = ((r0.x + r0.y) + (r0.z + r0.w)) + ((r1.x + r1.y) + (r1.z + r1.w))
                  + ((r2.x + r2.y) + (r2.z + r2.w)) + ((r3.x + r3.y) + (r3.z + r3.w));
        sum += __shfl_xor_sync(0xffffffffu, sum, 1);
        sum += __shfl_xor_sync(0xffffffffu, sum, 2);
        if (p == 0 && s2 < NS) scores[s2] = sum;
    }
    __syncthreads();

    // ---- softmax over S=50 (warp 0); Vr_b cancels; write probs scratch ----
    if (tid < 32) {
        float v0 = (tid      < NS) ? scores[tid]      : -1e30f;
        float v1 = (tid + 32 < NS) ? scores[tid + 32] : -1e30f;
        float m = fmaxf(v0, v1);
        #pragma unroll
        for (int o = 16; o; o >>= 1)
            m = fmaxf(m, __shfl_xor_sync(0xffffffffu, m, o));
        float e0 = (tid      < NS) ? __expf(v0 - m) : 0.f;
        float e1 = (tid + 32 < NS) ? __expf(v1 - m) : 0.f;
        float ssum = e0 + e1;
        #pragma unroll
        for (int o = 16; o; o >>= 1)
            ssum += __shfl_xor_sync(0xffffffffu, ssum, o);
        float inv = 1.f / ssum;
        if (tid      < NS) g_probs[b * NS + tid]      = e0 * inv;
        if (tid + 32 < NS) g_probs[b * NS + tid + 32] = e1 * inv;
    }
}

// ============ Kernel 2: scatter-add probs into zeroed output ============
__global__ __launch_bounds__(64)
void scatter_kernel(const int* __restrict__ seq_item, float* __restrict__ out)
{
    const int b = blockIdx.x;
    const int t = threadIdx.x;
    if (t < NS) {
        int item = seq_item[b * NS + t];
        atomicAdd(out + (size_t)b * NITEM + item, g_probs[b * NS + t]);
    }
}

extern "C" void kernel_launch(void* const* d_in, const int* in_sizes, int n_in,
                              void* d_out, int out_size)
{
    const float* all_memory  = (const float*)d_in[0];
    const float* last_memory = (const float*)d_in[1];
    const int*   seq_item    = (const int*)  d_in[2];
    const float* Wr          = (const float*)d_in[3];
    const float* Ur          = (const float*)d_in[4];
    const float* Vr_w        = (const float*)d_in[5];
    // d_in[6] = Vr_b — softmax shift-invariant, unused.
    float* out = (float*)d_out;

    fused_kernel<<<NB * STRIDE, TPB>>>(all_memory, last_memory, Wr, Ur, Vr_w, out);
    scatter_kernel<<<NB, 64>>>(seq_item, out);
}